// round 11
// baseline (speedup 1.0000x reference)
#include <cuda_runtime.h>
#include <cuda_fp16.h>
#include <cstdint>

#define BATCH 2048
#define TSEQ  100
#define DVAR  51
#define HID   128
#define G4    512
#define RPB   14
#define XTS   18
#define WSZ   (256*512)
#define NBLK  147
#define NTHR  512

#define GB_C   264
#define GB_RP  (4*GB_C)
#define GBUF   (7*GB_RP)

#define FWT_FLOATS (128*64)
#define D_SMEM_FLOATS (7*128*XTS + 4*GBUF + FWT_FLOATS)
#define D_SMEM_BYTES  (D_SMEM_FLOATS*4)
#define R_SMEM_FLOATS (2*128*XTS + 4*GBUF)
#define R_SMEM_BYTES  (R_SMEM_FLOATS*4)

// ---------------- device scratch ----------------
__device__ float  g_wt[6*WSZ + 8*G4];
__device__ float  g_fwt[FWT_FLOATS];
__device__ float  g_gx[(size_t)TSEQ*BATCH*G4];        // [m=t*2048+b][512]
__device__ float  g_hseq[(size_t)TSEQ*BATCH*HID];     // [m][128]
__device__ float  g_state[6*BATCH*HID];               // h0,h1,h2,c0,c1,c2
__device__ __half g_w16[3*512*128];                   // [l][j][k], zero-padded

typedef unsigned long long ull;

__device__ __forceinline__ ull dup2(float x) {
    ull r; asm("mov.b64 %0, {%1, %1};" : "=l"(r) : "f"(x)); return r;
}
__device__ __forceinline__ void fma2(ull& d, ull a, ull b) {
    asm("fma.rn.f32x2 %0, %1, %2, %0;" : "+l"(d) : "l"(a), "l"(b));
}
__device__ __forceinline__ void pfL1(const float* p) {
    asm volatile("prefetch.global.L1 [%0];" :: "l"(p));
}
__device__ __forceinline__ float sigf(float x) {
    return __fdividef(1.0f, 1.0f + __expf(-x));
}
__device__ __forceinline__ float tanhff(float x) {
    float e = __expf(2.0f * x);
    return 1.0f - __fdividef(2.0f, e + 1.0f);
}
__device__ __forceinline__ uint32_t smem_u32(const void* p) {
    uint32_t a;
    asm("{ .reg .u64 t; cvta.to.shared.u64 t, %1; cvt.u32.u64 %0, t; }" : "=r"(a) : "l"(p));
    return a;
}
__device__ __forceinline__ void ldsm4(uint32_t& r0, uint32_t& r1,
                                      uint32_t& r2, uint32_t& r3, uint32_t a) {
    asm volatile("ldmatrix.sync.aligned.m8n8.x4.shared.b16 {%0,%1,%2,%3}, [%4];"
                 : "=r"(r0), "=r"(r1), "=r"(r2), "=r"(r3) : "r"(a));
}
__device__ __forceinline__ void mma16816(float* d,
                                         uint32_t a0, uint32_t a1, uint32_t a2, uint32_t a3,
                                         uint32_t b0, uint32_t b1) {
    asm volatile(
        "mma.sync.aligned.m16n8k16.row.col.f32.f16.f16.f32 "
        "{%0,%1,%2,%3}, {%4,%5,%6,%7}, {%8,%9}, {%0,%1,%2,%3};"
        : "+f"(d[0]), "+f"(d[1]), "+f"(d[2]), "+f"(d[3])
        : "r"(a0), "r"(a1), "r"(a2), "r"(a3), "r"(b0), "r"(b1));
}

// ---------------------------------------------------------------------------
// Prep: fp32 transposed weights, fp16 Wih images, fW^T
// ---------------------------------------------------------------------------
__global__ void prep_kernel(
    const float* w0, const float* u0, const float* w1, const float* u1,
    const float* w2, const float* u2, const float* w3, const float* u3,
    const float* w4, const float* u4, const float* w5, const float* u5,
    const float* fW)
{
    const float* WIH[6] = {w0, w1, w2, w3, w4, w5};
    const float* WHH[6] = {u0, u1, u2, u3, u4, u5};
    const int total1 = 6*WSZ + 8*G4 + FWT_FLOATS;
    for (int idx = blockIdx.x*blockDim.x + threadIdx.x; idx < total1;
         idx += gridDim.x*blockDim.x) {
        if (idx < 6*WSZ) {
            int layer = idx / WSZ;
            int rem   = idx - layer*WSZ;
            int k = rem >> 9;
            int j = rem & 511;
            int din = (layer == 0 || layer == 3) ? DVAR : HID;
            float v;
            if (k < 128) v = (k < din) ? WIH[layer][j*din + k] : 0.0f;
            else         v = WHH[layer][j*HID + (k - 128)];
            g_wt[idx] = v;
        } else if (idx < 6*WSZ + 8*G4) {
            g_wt[idx] = 0.0f;
        } else {
            int r2 = idx - (6*WSZ + 8*G4);
            int u = r2 >> 6;
            int d = r2 & 63;
            g_fwt[r2] = (d < DVAR) ? fW[d*HID + u] : 0.0f;
        }
    }
    // fp16 Wih images, encoder layers 0..2: [l][j 0..511][k 0..127]
    const int total2 = 3*512*128;
    for (int idx = blockIdx.x*blockDim.x + threadIdx.x; idx < total2;
         idx += gridDim.x*blockDim.x) {
        int l = idx >> 16;
        int r = idx & 65535;
        int j = r >> 7;
        int k = r & 127;
        int din = (l == 0) ? DVAR : HID;
        g_w16[idx] = __float2half((k < din) ? WIH[l][j*din + k] : 0.0f);
    }
}

// ---------------------------------------------------------------------------
// Gx GEMM (HMMA): Gx[m0..+128, nb..+128] = X @ Wih^T. fp16 in, fp32 acc.
// MODE 0: X from src (layer0, KT=64); MODE 1/2: X = g_hseq (KT=128).
// 256 threads = 8 warps; warp w owns 16-row strip. ldmatrix + mma.m16n8k16.
// ---------------------------------------------------------------------------
template<int KT, int MODE>
__global__ void __launch_bounds__(256, 1) gx_kernel(const float* __restrict__ src)
{
    extern __shared__ __half smh[];
    constexpr int SA = KT + 8;              // padded half-stride (phase-free ldmatrix)
    __half* As = smh;                        // [128][SA]
    __half* Bs = smh + 128*SA;               // [128][SA]
    const int tid  = threadIdx.x;
    const int wid  = tid >> 5, lane = tid & 31;
    const int nb   = blockIdx.x * 128;       // n-tile (4)
    const int m0   = blockIdx.y * 128;       // m-tile (1600)

    // A: fp32 -> fp16 into padded smem
    for (int idx = tid; idx < 128*KT; idx += 256) {
        int r = idx / KT, k = idx - r*KT;
        float v;
        if (MODE == 0) {
            int m = m0 + r, b = m & (BATCH-1), t = m >> 11;
            v = (k < DVAR) ? src[(b*TSEQ + t)*DVAR + k] : 0.0f;
        } else {
            v = g_hseq[(size_t)(m0 + r)*HID + k];
        }
        As[r*SA + k] = __float2half(v);
    }
    // B: copy fp16 image rows nb..nb+127
    {
        const int L = (MODE == 0) ? 0 : MODE;
        const __half* ws = g_w16 + ((size_t)L*512 + nb)*128;
        for (int idx = tid; idx < 128*KT; idx += 256) {
            int r = idx / KT, k = idx - r*KT;
            Bs[r*SA + k] = ws[r*128 + k];
        }
    }
    __syncthreads();

    float acc[16][4];
#pragma unroll
    for (int i = 0; i < 16; i++)
#pragma unroll
        for (int q = 0; q < 4; q++) acc[i][q] = 0.0f;

    const uint32_t rsel = (lane & 15);
    const uint32_t csel = (uint32_t)(lane >> 4) * 8;
    const uint32_t aaddr = smem_u32(As) + (((uint32_t)wid*16 + rsel)*SA + csel)*2;
    const uint32_t baddr = smem_u32(Bs) + (rsel*SA + csel)*2;

#pragma unroll
    for (int ks = 0; ks < KT/16; ks++) {
        uint32_t a0, a1, a2, a3;
        ldsm4(a0, a1, a2, a3, aaddr + ks*32);
#pragma unroll
        for (int np = 0; np < 8; np++) {
            uint32_t b0, b1, b2, b3;
            ldsm4(b0, b1, b2, b3, baddr + (uint32_t)np*16*SA*2 + ks*32);
            mma16816(acc[2*np    ], a0, a1, a2, a3, b0, b2);
            mma16816(acc[2*np + 1], a0, a1, a2, a3, b1, b3);
        }
    }

    // epilogue: d-frag row = lane/4 (+8), col = nt*8 + 2*(lane%4)
    const int mrow = m0 + wid*16 + (lane >> 2);
    float* op  = g_gx + (size_t)mrow*G4 + nb + (lane & 3)*2;
    float* op2 = op + 8*(size_t)G4;
#pragma unroll
    for (int nt = 0; nt < 16; nt++) {
        *(float2*)(op  + nt*8) = make_float2(acc[nt][0], acc[nt][1]);
        *(float2*)(op2 + nt*8) = make_float2(acc[nt][2], acc[nt][3]);
    }
}

// ---------------------------------------------------------------------------
// fp32x2 scalar GEMM machinery (R9, unchanged)
// ---------------------------------------------------------------------------
__device__ __forceinline__ void kstep(float4 cur, const float* xk,
                                      ull* acc, ull* xv)
{
    ull w0 = dup2(cur.x), w1 = dup2(cur.y), w2 = dup2(cur.z), w3 = dup2(cur.w);
#pragma unroll
    for (int rp = 0; rp < 7; rp++) {
        fma2(acc[rp],      xv[rp], w0);
        fma2(acc[7 + rp],  xv[rp], w1);
        fma2(acc[14 + rp], xv[rp], w2);
        fma2(acc[21 + rp], xv[rp], w3);
        xv[rp] = *(const ull*)(xk + 2*rp);
    }
}

template<int K>
__device__ __forceinline__ void gpart(const float* __restrict__ wp,
                                      const float* xin, const float* xnext,
                                      ull* acc, ull* xv, float4* W,
                                      const float* __restrict__ wnext)
{
#pragma unroll 1
    for (int kg = 0; kg < K/4 - 1; kg++) {
#pragma unroll
        for (int q = 0; q < 4; q++) {
            const int k = 4*kg + q;
            float4 cur = W[q];
            W[q] = *(const float4*)(wp + (k + 4)*G4);
            kstep(cur, xin + (k + 1)*XTS, acc, xv);
        }
    }
#pragma unroll
    for (int q = 0; q < 4; q++) {
        const int k = K - 4 + q;
        float4 cur = W[q];
        W[q] = *(const float4*)(wnext + q*G4);
        kstep(cur, (q == 3) ? xnext : xin + (k + 1)*XTS, acc, xv);
    }
}

template<int KIN, int KA3>
__device__ __noinline__ void cell(const float* __restrict__ wt,
                                  const float* __restrict__ bias,
                                  const float* xin, float* h, float* c,
                                  float* gb, int tid,
                                  const float* __restrict__ wnext, int knext)
{
    const int set = tid >> 7;
    const int t   = tid & 127;
    const int j0  = t << 2;
    constexpr int KA = KIN/4;
    const int kst = set*KA;

    const float* wpA = wt + kst*G4 + j0;
    const float* wpB = wt + (128 + set*32)*G4 + j0;
    const float* xA  = xin + kst*XTS;
    const float* xB  = h + (set*32)*XTS;

    float4 W[4];
#pragma unroll
    for (int q = 0; q < 4; q++) W[q] = *(const float4*)(wpA + q*G4);
    ull xv[7];
#pragma unroll
    for (int rp = 0; rp < 7; rp++) xv[rp] = *(const ull*)(xA + 2*rp);

    ull acc[28];
    if (set == 0) {
        float4 bv = *(const float4*)(bias + j0);
#pragma unroll
        for (int rp = 0; rp < 7; rp++) {
            acc[rp] = dup2(bv.x); acc[7+rp] = dup2(bv.y);
            acc[14+rp] = dup2(bv.z); acc[21+rp] = dup2(bv.w);
        }
    } else {
#pragma unroll
        for (int i = 0; i < 28; i++) acc[i] = 0ull;
    }

    if (KA3 == KA || set < 3) {
        gpart<KA>(wpA, xA, xB, acc, xv, W, wpB);
    } else {
        gpart<KA3>(wpA, xA, xB, acc, xv, W, wpB);
    }
    gpart<32>(wpB, xB, xB, acc, xv, W, wpB);

    float* gs = gb + set*GBUF;
#pragma unroll
    for (int cc = 0; cc < 4; cc++)
#pragma unroll
        for (int rp = 0; rp < 7; rp++)
            *(ull*)(gs + rp*GB_RP + cc*GB_C + t*2) = acc[cc*7 + rp];

    {
        const float* pf = wnext + (set*knext)*G4 + j0;
#pragma unroll
        for (int q = 0; q < 4; q++) pfL1(pf + q*G4);
    }
    __syncthreads();

#pragma unroll
    for (int it = 0; it < 2; it++) {
        int idx = tid + it*NTHR;
        if (idx < 896) {
            int u  = idx & 127;
            int rp = idx >> 7;
            int cb = rp*GB_RP + (u & 3)*GB_C + (u >> 2)*2;
            float2 gi = {0.f,0.f}, gf = {0.f,0.f}, gg = {0.f,0.f}, go = {0.f,0.f};
#pragma unroll
            for (int s = 0; s < 4; s++) {
                const float* g = gb + s*GBUF + cb;
                float2 a = *(const float2*)(g      );
                float2 b = *(const float2*)(g +  64);
                float2 d = *(const float2*)(g + 128);
                float2 e = *(const float2*)(g + 192);
                gi.x += a.x; gi.y += a.y;
                gf.x += b.x; gf.y += b.y;
                gg.x += d.x; gg.y += d.y;
                go.x += e.x; go.y += e.y;
            }
            float2 cc2 = *(const float2*)(c + u*XTS + 2*rp);
            float2 cn, hn;
            cn.x = sigf(gf.x)*cc2.x + sigf(gi.x)*tanhff(gg.x);
            cn.y = sigf(gf.y)*cc2.y + sigf(gi.y)*tanhff(gg.y);
            hn.x = sigf(go.x)*tanhff(cn.x);
            hn.y = sigf(go.y)*tanhff(cn.y);
            *(float2*)(c + u*XTS + 2*rp) = cn;
            *(float2*)(h + u*XTS + 2*rp) = hn;
        }
    }
    __syncthreads();
}

// ---------------------------------------------------------------------------
// Encoder recurrent kernel for one layer: h-part GEMM only; EW adds Gx.
// ---------------------------------------------------------------------------
__global__ void __launch_bounds__(NTHR, 1) rec_kernel(
    int layer, const float* __restrict__ bias, int writeseq)
{
    extern __shared__ float sm[];
    float* h  = sm;
    float* c  = sm + 128*XTS;
    float* gb = sm + 2*128*XTS;

    const int tid = threadIdx.x;
    const int b0  = blockIdx.x * RPB;
    const float* wt = g_wt + layer*WSZ;

    for (int i = tid; i < 2*128*XTS; i += NTHR) sm[i] = 0.0f;
    __syncthreads();

    const int set = tid >> 7;
    const int t5  = tid & 127;
    const int j0  = t5 << 2;
    const float* wpB = wt + (128 + set*32)*G4 + j0;
    const float* xB  = h + (set*32)*XTS;

    for (int t = 0; t < TSEQ; t++) {
        float4 W[4];
#pragma unroll
        for (int q = 0; q < 4; q++) W[q] = *(const float4*)(wpB + q*G4);
        ull xv[7];
#pragma unroll
        for (int rp = 0; rp < 7; rp++) xv[rp] = *(const ull*)(xB + 2*rp);
        ull acc[28];
        if (set == 0) {
            float4 bv = *(const float4*)(bias + j0);
#pragma unroll
            for (int rp = 0; rp < 7; rp++) {
                acc[rp] = dup2(bv.x); acc[7+rp] = dup2(bv.y);
                acc[14+rp] = dup2(bv.z); acc[21+rp] = dup2(bv.w);
            }
        } else {
#pragma unroll
            for (int i = 0; i < 28; i++) acc[i] = 0ull;
        }
        gpart<32>(wpB, xB, xB, acc, xv, W, wpB);

        float* gs = gb + set*GBUF;
#pragma unroll
        for (int cc = 0; cc < 4; cc++)
#pragma unroll
            for (int rp = 0; rp < 7; rp++)
                *(ull*)(gs + rp*GB_RP + cc*GB_C + t5*2) = acc[cc*7 + rp];
        __syncthreads();

#pragma unroll
        for (int it = 0; it < 2; it++) {
            int idx = tid + it*NTHR;
            if (idx < 896) {
                int u  = idx & 127;
                int rp = idx >> 7;
                int cb = rp*GB_RP + (u & 3)*GB_C + (u >> 2)*2;
                float2 gi = {0.f,0.f}, gf = {0.f,0.f}, gg = {0.f,0.f}, go = {0.f,0.f};
#pragma unroll
                for (int s = 0; s < 4; s++) {
                    const float* g = gb + s*GBUF + cb;
                    float2 a = *(const float2*)(g      );
                    float2 b = *(const float2*)(g +  64);
                    float2 d = *(const float2*)(g + 128);
                    float2 e = *(const float2*)(g + 192);
                    gi.x += a.x; gi.y += a.y;
                    gf.x += b.x; gf.y += b.y;
                    gg.x += d.x; gg.y += d.y;
                    go.x += e.x; go.y += e.y;
                }
                int r0 = 2*rp, r1 = r0 + 1;
                int bb0 = b0 + r0; if (bb0 >= BATCH) bb0 = BATCH - 1;
                int bb1 = b0 + r1; if (bb1 >= BATCH) bb1 = BATCH - 1;
                const float* gx0 = g_gx + ((size_t)t*BATCH + bb0)*G4;
                const float* gx1 = g_gx + ((size_t)t*BATCH + bb1)*G4;
                gi.x += gx0[u];        gi.y += gx1[u];
                gf.x += gx0[128 + u];  gf.y += gx1[128 + u];
                gg.x += gx0[256 + u];  gg.y += gx1[256 + u];
                go.x += gx0[384 + u];  go.y += gx1[384 + u];

                float2 cc2 = *(const float2*)(c + u*XTS + 2*rp);
                float2 cn, hn;
                cn.x = sigf(gf.x)*cc2.x + sigf(gi.x)*tanhff(gg.x);
                cn.y = sigf(gf.y)*cc2.y + sigf(gi.y)*tanhff(gg.y);
                hn.x = sigf(go.x)*tanhff(cn.x);
                hn.y = sigf(go.y)*tanhff(cn.y);
                *(float2*)(c + u*XTS + 2*rp) = cn;
                *(float2*)(h + u*XTS + 2*rp) = hn;

                if (writeseq) {
                    g_hseq[((size_t)t*BATCH + bb0)*HID + u] = hn.x;
                    g_hseq[((size_t)t*BATCH + bb1)*HID + u] = hn.y;
                }
                if (t == TSEQ - 1) {
                    g_state[(layer    )*BATCH*HID + bb0*HID + u] = hn.x;
                    g_state[(layer    )*BATCH*HID + bb1*HID + u] = hn.y;
                    g_state[(3 + layer)*BATCH*HID + bb0*HID + u] = cn.x;
                    g_state[(3 + layer)*BATCH*HID + bb1*HID + u] = cn.y;
                }
            }
        }
        __syncthreads();
    }
}

// ---------------------------------------------------------------------------
// Decoder persistent kernel (state loaded from g_state).
// ---------------------------------------------------------------------------
__global__ void __launch_bounds__(NTHR, 1) dec_kernel(
    const float* __restrict__ db0, const float* __restrict__ db1,
    const float* __restrict__ db2, const float* __restrict__ fb,
    float* __restrict__ out)
{
    extern __shared__ float sm[];
    float* xt   = sm;
    float* h0   = sm + 1*128*XTS;
    float* h1   = sm + 2*128*XTS;
    float* h2   = sm + 3*128*XTS;
    float* c0   = sm + 4*128*XTS;
    float* c1   = sm + 5*128*XTS;
    float* c2   = sm + 6*128*XTS;
    float* gb   = sm + 7*128*XTS;
    float* fwts = gb + 4*GBUF;

    const int tid = threadIdx.x;
    const int b0  = blockIdx.x * RPB;

    for (int i = tid; i < 7*128*XTS; i += NTHR) sm[i] = 0.0f;
    for (int i = tid; i < FWT_FLOATS; i += NTHR) fwts[i] = g_fwt[i];
    __syncthreads();

    float* HP[3] = {h0, h1, h2};
    float* CP[3] = {c0, c1, c2};
#pragma unroll
    for (int l = 0; l < 3; l++) {
        for (int i = tid; i < 128*RPB; i += NTHR) {
            int u = i & 127;
            int r = i >> 7;
            int b = b0 + r; if (b >= BATCH) b = BATCH - 1;
            HP[l][u*XTS + r] = g_state[(l    )*BATCH*HID + b*HID + u];
            CP[l][u*XTS + r] = g_state[(3 + l)*BATCH*HID + b*HID + u];
        }
    }
    __syncthreads();

    for (int t = 0; t < TSEQ; t++) {
        cell<64 , 4>(g_wt + 3*WSZ, db0, xt, h0, c0, gb, tid, g_wt + 4*WSZ, 32);
        cell<128,32>(g_wt + 4*WSZ, db1, h0, h1, c1, gb, tid, g_wt + 5*WSZ, 32);
        cell<128,32>(g_wt + 5*WSZ, db2, h1, h2, c2, gb, tid, g_wt + 3*WSZ, 16);

        {
            int d  = tid & 63;
            int rg = tid >> 6;
            float fbv = (d < DVAR) ? fb[d] : 0.0f;
            float a0 = fbv, a1 = fbv;
            int r0 = rg, r1 = rg + 8;
#pragma unroll 4
            for (int u = 0; u < HID; u++) {
                float wv = fwts[(u << 6) + d];
                a0 += h2[u*XTS + r0] * wv;
                a1 += h2[u*XTS + r1] * wv;
            }
            if (d < DVAR) {
                xt[d*XTS + r0] = a0;
                int bb = b0 + r0;
                if (bb < BATCH)
                    out[(bb*TSEQ + (TSEQ - 1 - t))*DVAR + d] = a0;
                if (r1 < RPB) {
                    xt[d*XTS + r1] = a1;
                    int bb1 = b0 + r1;
                    if (bb1 < BATCH)
                        out[(bb1*TSEQ + (TSEQ - 1 - t))*DVAR + d] = a1;
                }
            }
        }
        __syncthreads();
    }
}

// ---------------------------------------------------------------------------
extern "C" void kernel_launch(void* const* d_in, const int* in_sizes, int n_in,
                              void* d_out, int out_size)
{
    const float* src = (const float*)d_in[0];
    const float* eW0 = (const float*)d_in[1];
    const float* eU0 = (const float*)d_in[2];
    const float* eb0 = (const float*)d_in[3];
    const float* eW1 = (const float*)d_in[4];
    const float* eU1 = (const float*)d_in[5];
    const float* eb1 = (const float*)d_in[6];
    const float* eW2 = (const float*)d_in[7];
    const float* eU2 = (const float*)d_in[8];
    const float* eb2 = (const float*)d_in[9];
    const float* dW0 = (const float*)d_in[10];
    const float* dU0 = (const float*)d_in[11];
    const float* db0 = (const float*)d_in[12];
    const float* dW1 = (const float*)d_in[13];
    const float* dU1 = (const float*)d_in[14];
    const float* db1 = (const float*)d_in[15];
    const float* dW2 = (const float*)d_in[16];
    const float* dU2 = (const float*)d_in[17];
    const float* db2 = (const float*)d_in[18];
    const float* fW  = (const float*)d_in[19];
    const float* fb  = (const float*)d_in[20];
    float* out = (float*)d_out;

    const int GX64_SMEM  = 2*128*(64 + 8)*2;    // 36864
    const int GX128_SMEM = 2*128*(128 + 8)*2;   // 69632

    cudaFuncSetAttribute(gx_kernel<64,0>,  cudaFuncAttributeMaxDynamicSharedMemorySize, GX64_SMEM);
    cudaFuncSetAttribute(gx_kernel<128,1>, cudaFuncAttributeMaxDynamicSharedMemorySize, GX128_SMEM);
    cudaFuncSetAttribute(gx_kernel<128,2>, cudaFuncAttributeMaxDynamicSharedMemorySize, GX128_SMEM);
    cudaFuncSetAttribute(rec_kernel, cudaFuncAttributeMaxDynamicSharedMemorySize, R_SMEM_BYTES);
    cudaFuncSetAttribute(dec_kernel, cudaFuncAttributeMaxDynamicSharedMemorySize, D_SMEM_BYTES);

    prep_kernel<<<1024, 256>>>(eW0, eU0, eW1, eU1, eW2, eU2,
                               dW0, dU0, dW1, dU1, dW2, dU2, fW);

    dim3 gxgrid(4, 1600);
    gx_kernel<64,0><<<gxgrid, 256, GX64_SMEM>>>(src);
    rec_kernel<<<NBLK, NTHR, R_SMEM_BYTES>>>(0, eb0, 1);
    gx_kernel<128,1><<<gxgrid, 256, GX128_SMEM>>>(src);
    rec_kernel<<<NBLK, NTHR, R_SMEM_BYTES>>>(1, eb1, 1);
    gx_kernel<128,2><<<gxgrid, 256, GX128_SMEM>>>(src);
    rec_kernel<<<NBLK, NTHR, R_SMEM_BYTES>>>(2, eb2, 0);
    dec_kernel<<<NBLK, NTHR, D_SMEM_BYTES>>>(db0, db1, db2, fb, out);
}

// round 12
// speedup vs baseline: 1.4526x; 1.4526x over previous
#include <cuda_runtime.h>
#include <cuda_fp16.h>
#include <cstdint>

#define BATCH 2048
#define TSEQ  100
#define DVAR  51
#define HID   128
#define G4    512
#define RPB   14
#define XTS   18
#define WSZ   (256*512)
#define NBLK  147
#define NTHR  512

#define GB_C   264
#define GB_RP  (4*GB_C)
#define GBUF   (7*GB_RP)

#define FWT_FLOATS (128*64)
#define R_SMEM_FLOATS (2*128*XTS + 4*GBUF)
#define R_SMEM_BYTES  (R_SMEM_FLOATS*4)

// ---- decoder HMMA smem map (bytes) ----
#define OFF_FWT   0u          /* 8192 f32  = 32768 */
#define OFF_BIAS  32768u      /* 3*512 f32 = 6144  */
#define OFF_A0H   38912u      /* 16*200 h  = 6400  */
#define OFF_A0L   45312u
#define OFF_A1H   51712u      /* 16*264 h  = 8448  */
#define OFF_A1L   60160u
#define OFF_A2H   68608u
#define OFF_A2L   77056u
#define OFF_GATES 85504u      /* 16*520 f32 = 33280 */
#define OFF_C0    118784u     /* 16*132 f32 = 8448, x3 */
#define OFF_H2    144128u     /* 16*132 f32 = 8448 */
#define DEC_SMEM  152576

// ---------------- device scratch ----------------
__device__ float  g_wt[6*WSZ + 8*G4];
__device__ float  g_fwt[FWT_FLOATS];
__device__ float  g_gx[(size_t)TSEQ*BATCH*G4];        // [m=t*2048+b][512]
__device__ float  g_hseq[(size_t)TSEQ*BATCH*HID];     // [m][128]
__device__ float  g_state[6*BATCH*HID];               // h0,h1,h2,c0,c1,c2
__device__ __half g_w16[3*512*128];                   // encoder Wih fp16 [l][j][k]
__device__ uint2  g_wd[45*2048];                      // decoder fp16 B-frag pack (+1 ksb pad)

typedef unsigned long long ull;

__device__ __forceinline__ ull dup2(float x) {
    ull r; asm("mov.b64 %0, {%1, %1};" : "=l"(r) : "f"(x)); return r;
}
__device__ __forceinline__ void fma2(ull& d, ull a, ull b) {
    asm("fma.rn.f32x2 %0, %1, %2, %0;" : "+l"(d) : "l"(a), "l"(b));
}
__device__ __forceinline__ float sigf(float x) {
    return __fdividef(1.0f, 1.0f + __expf(-x));
}
__device__ __forceinline__ float tanhff(float x) {
    float e = __expf(2.0f * x);
    return 1.0f - __fdividef(2.0f, e + 1.0f);
}
__device__ __forceinline__ uint32_t smem_u32(const void* p) {
    uint32_t a;
    asm("{ .reg .u64 t; cvta.to.shared.u64 t, %1; cvt.u32.u64 %0, t; }" : "=r"(a) : "l"(p));
    return a;
}
__device__ __forceinline__ void ldsm4(uint32_t& r0, uint32_t& r1,
                                      uint32_t& r2, uint32_t& r3, uint32_t a) {
    asm volatile("ldmatrix.sync.aligned.m8n8.x4.shared.b16 {%0,%1,%2,%3}, [%4];"
                 : "=r"(r0), "=r"(r1), "=r"(r2), "=r"(r3) : "r"(a));
}
__device__ __forceinline__ void mma16816(float* d,
                                         uint32_t a0, uint32_t a1, uint32_t a2, uint32_t a3,
                                         uint32_t b0, uint32_t b1) {
    asm volatile(
        "mma.sync.aligned.m16n8k16.row.col.f32.f16.f16.f32 "
        "{%0,%1,%2,%3}, {%4,%5,%6,%7}, {%8,%9}, {%0,%1,%2,%3};"
        : "+f"(d[0]), "+f"(d[1]), "+f"(d[2]), "+f"(d[3])
        : "r"(a0), "r"(a1), "r"(a2), "r"(a3), "r"(b0), "r"(b1));
}

// ---------------------------------------------------------------------------
// Prep: fp32 transposed weights (encoder rec), fp16 Wih images (gx),
// fW^T, and decoder fp16 B-fragment-packed weights.
// ---------------------------------------------------------------------------
__global__ void prep_kernel(
    const float* w0, const float* u0, const float* w1, const float* u1,
    const float* w2, const float* u2, const float* w3, const float* u3,
    const float* w4, const float* u4, const float* w5, const float* u5,
    const float* fW)
{
    const float* WIH[6] = {w0, w1, w2, w3, w4, w5};
    const float* WHH[6] = {u0, u1, u2, u3, u4, u5};
    const int total1 = 6*WSZ + 8*G4 + FWT_FLOATS;
    for (int idx = blockIdx.x*blockDim.x + threadIdx.x; idx < total1;
         idx += gridDim.x*blockDim.x) {
        if (idx < 6*WSZ) {
            int layer = idx / WSZ;
            int rem   = idx - layer*WSZ;
            int k = rem >> 9;
            int j = rem & 511;
            int din = (layer == 0 || layer == 3) ? DVAR : HID;
            float v;
            if (k < 128) v = (k < din) ? WIH[layer][j*din + k] : 0.0f;
            else         v = WHH[layer][j*HID + (k - 128)];
            g_wt[idx] = v;
        } else if (idx < 6*WSZ + 8*G4) {
            g_wt[idx] = 0.0f;
        } else {
            int r2 = idx - (6*WSZ + 8*G4);
            int u = r2 >> 6;
            int d = r2 & 63;
            g_fwt[r2] = (d < DVAR) ? fW[d*HID + u] : 0.0f;
        }
    }
    // fp16 Wih images (encoder gx): [l][j 0..511][k 0..127]
    const int total2 = 3*512*128;
    for (int idx = blockIdx.x*blockDim.x + threadIdx.x; idx < total2;
         idx += gridDim.x*blockDim.x) {
        int l = idx >> 16;
        int r = idx & 65535;
        int j = r >> 7;
        int k = r & 127;
        int din = (l == 0) ? DVAR : HID;
        g_w16[idx] = __float2half((k < din) ? WIH[l][j*din + k] : 0.0f);
    }
    // decoder fp16 B-fragment pack: element e = (ksg, n, q) -> 4 halves
    // b0 = {W[n][k0], W[n][k0+1]}, b1 = {W[n][k0+8], W[n][k0+9]}, k0 = ks*16+q*2
    const int total3 = 45*2048;
    for (int e = blockIdx.x*blockDim.x + threadIdx.x; e < total3;
         e += gridDim.x*blockDim.x) {
        int ksg = e >> 11;
        int r   = e & 2047;
        int n   = r >> 2;
        int q   = r & 3;
        unsigned short h4[4];
#pragma unroll
        for (int i = 0; i < 4; i++) {
            float v = 0.0f;
            if (ksg < 44) {
                int dl, ksl, kin, din;
                if (ksg < 12)      { dl = 0; ksl = ksg;      kin = 64;  din = DVAR; }
                else if (ksg < 28) { dl = 1; ksl = ksg - 12; kin = 128; din = HID; }
                else               { dl = 2; ksl = ksg - 28; kin = 128; din = HID; }
                int k = ksl*16 + q*2 + (i & 1) + ((i >> 1) << 3);
                const float* Wx = (dl == 0) ? w3 : (dl == 1) ? w4 : w5;
                const float* Wh = (dl == 0) ? u3 : (dl == 1) ? u4 : u5;
                if (k < kin) v = (k < din) ? Wx[n*din + k] : 0.0f;
                else         v = Wh[n*HID + (k - kin)];
            }
            __half hv = __float2half(v);
            h4[i] = __half_as_ushort(hv);
        }
        uint2 pk;
        pk.x = (uint32_t)h4[0] | ((uint32_t)h4[1] << 16);
        pk.y = (uint32_t)h4[2] | ((uint32_t)h4[3] << 16);
        g_wd[e] = pk;
    }
}

// ---------------------------------------------------------------------------
// Gx GEMM (HMMA) — unchanged from R11 (validated).
// ---------------------------------------------------------------------------
template<int KT, int MODE>
__global__ void __launch_bounds__(256, 1) gx_kernel(const float* __restrict__ src)
{
    extern __shared__ __half smh[];
    constexpr int SA = KT + 8;
    __half* As = smh;
    __half* Bs = smh + 128*SA;
    const int tid  = threadIdx.x;
    const int wid  = tid >> 5, lane = tid & 31;
    const int nb   = blockIdx.x * 128;
    const int m0   = blockIdx.y * 128;

    for (int idx = tid; idx < 128*KT; idx += 256) {
        int r = idx / KT, k = idx - r*KT;
        float v;
        if (MODE == 0) {
            int m = m0 + r, b = m & (BATCH-1), t = m >> 11;
            v = (k < DVAR) ? src[(b*TSEQ + t)*DVAR + k] : 0.0f;
        } else {
            v = g_hseq[(size_t)(m0 + r)*HID + k];
        }
        As[r*SA + k] = __float2half(v);
    }
    {
        const int L = (MODE == 0) ? 0 : MODE;
        const __half* ws = g_w16 + ((size_t)L*512 + nb)*128;
        for (int idx = tid; idx < 128*KT; idx += 256) {
            int r = idx / KT, k = idx - r*KT;
            Bs[r*SA + k] = ws[r*128 + k];
        }
    }
    __syncthreads();

    float acc[16][4];
#pragma unroll
    for (int i = 0; i < 16; i++)
#pragma unroll
        for (int q = 0; q < 4; q++) acc[i][q] = 0.0f;

    const uint32_t rsel = (lane & 15);
    const uint32_t csel = (uint32_t)(lane >> 4) * 8;
    const uint32_t aaddr = smem_u32(As) + (((uint32_t)wid*16 + rsel)*SA + csel)*2;
    const uint32_t baddr = smem_u32(Bs) + (rsel*SA + csel)*2;

#pragma unroll
    for (int ks = 0; ks < KT/16; ks++) {
        uint32_t a0, a1, a2, a3;
        ldsm4(a0, a1, a2, a3, aaddr + ks*32);
#pragma unroll
        for (int np = 0; np < 8; np++) {
            uint32_t b0, b1, b2, b3;
            ldsm4(b0, b1, b2, b3, baddr + (uint32_t)np*16*SA*2 + ks*32);
            mma16816(acc[2*np    ], a0, a1, a2, a3, b0, b2);
            mma16816(acc[2*np + 1], a0, a1, a2, a3, b1, b3);
        }
    }

    const int mrow = m0 + wid*16 + (lane >> 2);
    float* op  = g_gx + (size_t)mrow*G4 + nb + (lane & 3)*2;
    float* op2 = op + 8*(size_t)G4;
#pragma unroll
    for (int nt = 0; nt < 16; nt++) {
        *(float2*)(op  + nt*8) = make_float2(acc[nt][0], acc[nt][1]);
        *(float2*)(op2 + nt*8) = make_float2(acc[nt][2], acc[nt][3]);
    }
}

// ---------------------------------------------------------------------------
// fp32x2 scalar machinery for the encoder rec kernel (validated, unchanged)
// ---------------------------------------------------------------------------
__device__ __forceinline__ void kstep(float4 cur, const float* xk,
                                      ull* acc, ull* xv)
{
    ull w0 = dup2(cur.x), w1 = dup2(cur.y), w2 = dup2(cur.z), w3 = dup2(cur.w);
#pragma unroll
    for (int rp = 0; rp < 7; rp++) {
        fma2(acc[rp],      xv[rp], w0);
        fma2(acc[7 + rp],  xv[rp], w1);
        fma2(acc[14 + rp], xv[rp], w2);
        fma2(acc[21 + rp], xv[rp], w3);
        xv[rp] = *(const ull*)(xk + 2*rp);
    }
}

template<int K>
__device__ __forceinline__ void gpart(const float* __restrict__ wp,
                                      const float* xin, const float* xnext,
                                      ull* acc, ull* xv, float4* W,
                                      const float* __restrict__ wnext)
{
#pragma unroll 1
    for (int kg = 0; kg < K/4 - 1; kg++) {
#pragma unroll
        for (int q = 0; q < 4; q++) {
            const int k = 4*kg + q;
            float4 cur = W[q];
            W[q] = *(const float4*)(wp + (k + 4)*G4);
            kstep(cur, xin + (k + 1)*XTS, acc, xv);
        }
    }
#pragma unroll
    for (int q = 0; q < 4; q++) {
        const int k = K - 4 + q;
        float4 cur = W[q];
        W[q] = *(const float4*)(wnext + q*G4);
        kstep(cur, (q == 3) ? xnext : xin + (k + 1)*XTS, acc, xv);
    }
}

// ---------------------------------------------------------------------------
// Encoder recurrent kernel — unchanged from R11.
// ---------------------------------------------------------------------------
__global__ void __launch_bounds__(NTHR, 1) rec_kernel(
    int layer, const float* __restrict__ bias, int writeseq)
{
    extern __shared__ float sm[];
    float* h  = sm;
    float* c  = sm + 128*XTS;
    float* gb = sm + 2*128*XTS;

    const int tid = threadIdx.x;
    const int b0  = blockIdx.x * RPB;
    const float* wt = g_wt + layer*WSZ;

    for (int i = tid; i < 2*128*XTS; i += NTHR) sm[i] = 0.0f;
    __syncthreads();

    const int set = tid >> 7;
    const int t5  = tid & 127;
    const int j0  = t5 << 2;
    const float* wpB = wt + (128 + set*32)*G4 + j0;
    const float* xB  = h + (set*32)*XTS;

    for (int t = 0; t < TSEQ; t++) {
        float4 W[4];
#pragma unroll
        for (int q = 0; q < 4; q++) W[q] = *(const float4*)(wpB + q*G4);
        ull xv[7];
#pragma unroll
        for (int rp = 0; rp < 7; rp++) xv[rp] = *(const ull*)(xB + 2*rp);
        ull acc[28];
        if (set == 0) {
            float4 bv = *(const float4*)(bias + j0);
#pragma unroll
            for (int rp = 0; rp < 7; rp++) {
                acc[rp] = dup2(bv.x); acc[7+rp] = dup2(bv.y);
                acc[14+rp] = dup2(bv.z); acc[21+rp] = dup2(bv.w);
            }
        } else {
#pragma unroll
            for (int i = 0; i < 28; i++) acc[i] = 0ull;
        }
        gpart<32>(wpB, xB, xB, acc, xv, W, wpB);

        float* gs = gb + set*GBUF;
#pragma unroll
        for (int cc = 0; cc < 4; cc++)
#pragma unroll
            for (int rp = 0; rp < 7; rp++)
                *(ull*)(gs + rp*GB_RP + cc*GB_C + t5*2) = acc[cc*7 + rp];
        __syncthreads();

#pragma unroll
        for (int it = 0; it < 2; it++) {
            int idx = tid + it*NTHR;
            if (idx < 896) {
                int u  = idx & 127;
                int rp = idx >> 7;
                int cb = rp*GB_RP + (u & 3)*GB_C + (u >> 2)*2;
                float2 gi = {0.f,0.f}, gf = {0.f,0.f}, gg = {0.f,0.f}, go = {0.f,0.f};
#pragma unroll
                for (int s = 0; s < 4; s++) {
                    const float* g = gb + s*GBUF + cb;
                    float2 a = *(const float2*)(g      );
                    float2 b = *(const float2*)(g +  64);
                    float2 d = *(const float2*)(g + 128);
                    float2 e = *(const float2*)(g + 192);
                    gi.x += a.x; gi.y += a.y;
                    gf.x += b.x; gf.y += b.y;
                    gg.x += d.x; gg.y += d.y;
                    go.x += e.x; go.y += e.y;
                }
                int r0 = 2*rp, r1 = r0 + 1;
                int bb0 = b0 + r0; if (bb0 >= BATCH) bb0 = BATCH - 1;
                int bb1 = b0 + r1; if (bb1 >= BATCH) bb1 = BATCH - 1;
                const float* gx0 = g_gx + ((size_t)t*BATCH + bb0)*G4;
                const float* gx1 = g_gx + ((size_t)t*BATCH + bb1)*G4;
                gi.x += gx0[u];        gi.y += gx1[u];
                gf.x += gx0[128 + u];  gf.y += gx1[128 + u];
                gg.x += gx0[256 + u];  gg.y += gx1[256 + u];
                go.x += gx0[384 + u];  go.y += gx1[384 + u];

                float2 cc2 = *(const float2*)(c + u*XTS + 2*rp);
                float2 cn, hn;
                cn.x = sigf(gf.x)*cc2.x + sigf(gi.x)*tanhff(gg.x);
                cn.y = sigf(gf.y)*cc2.y + sigf(gi.y)*tanhff(gg.y);
                hn.x = sigf(go.x)*tanhff(cn.x);
                hn.y = sigf(go.y)*tanhff(cn.y);
                *(float2*)(c + u*XTS + 2*rp) = cn;
                *(float2*)(h + u*XTS + 2*rp) = hn;

                if (writeseq) {
                    g_hseq[((size_t)t*BATCH + bb0)*HID + u] = hn.x;
                    g_hseq[((size_t)t*BATCH + bb1)*HID + u] = hn.y;
                }
                if (t == TSEQ - 1) {
                    g_state[(layer    )*BATCH*HID + bb0*HID + u] = hn.x;
                    g_state[(layer    )*BATCH*HID + bb1*HID + u] = hn.y;
                    g_state[(3 + layer)*BATCH*HID + bb0*HID + u] = cn.x;
                    g_state[(3 + layer)*BATCH*HID + bb1*HID + u] = cn.y;
                }
            }
        }
        __syncthreads();
    }
}

// ---------------------------------------------------------------------------
// Decoder HMMA GEMM: gates[16][512] = A(hi+lo) @ B(fp16), B straight from L2.
// 16 warps, warp w owns n in [w*32, w*32+32). A broadcast via ldmatrix.
// ---------------------------------------------------------------------------
template<int KS, int SA>
__device__ __forceinline__ void dec_gemm(char* smem, uint32_t ahi_off,
                                         uint32_t alo_off,
                                         const uint2* __restrict__ wd, int tid)
{
    const int lane  = tid & 31;
    const int wbase = (tid >> 5) * 4;      // global n8-tile base for this warp

    float acc[16];
#pragma unroll
    for (int i = 0; i < 16; i++) acc[i] = 0.0f;

    const uint2* bp = wd + wbase*32 + lane;
    uint2 bc[4];
#pragma unroll
    for (int nt = 0; nt < 4; nt++) bc[nt] = bp[nt*32];

    const uint32_t abase = smem_u32(smem) + ((lane & 15)*SA + (lane >> 4)*8)*2;
    const uint32_t ahi = abase + ahi_off;
    const uint32_t alo = abase + alo_off;

#pragma unroll
    for (int ks = 0; ks < KS; ks++) {
        uint2 bn[4];
#pragma unroll
        for (int nt = 0; nt < 4; nt++) bn[nt] = bp[(ks + 1)*2048 + nt*32]; // pad-safe
        uint32_t ah0, ah1, ah2, ah3, al0, al1, al2, al3;
        ldsm4(ah0, ah1, ah2, ah3, ahi + ks*32);
        ldsm4(al0, al1, al2, al3, alo + ks*32);
#pragma unroll
        for (int nt = 0; nt < 4; nt++) {
            mma16816(acc + nt*4, ah0, ah1, ah2, ah3, bc[nt].x, bc[nt].y);
            mma16816(acc + nt*4, al0, al1, al2, al3, bc[nt].x, bc[nt].y);
        }
#pragma unroll
        for (int nt = 0; nt < 4; nt++) bc[nt] = bn[nt];
    }

    // scatter to gates[16][520]
    float* gates = (float*)(smem + OFF_GATES);
    const int row0 = lane >> 2;
    const int colb = wbase*8 + (lane & 3)*2;
#pragma unroll
    for (int nt = 0; nt < 4; nt++)
#pragma unroll
        for (int q = 0; q < 2; q++)
            *(float2*)(gates + (row0 + q*8)*520 + colb + nt*8)
                = make_float2(acc[nt*4 + 2*q], acc[nt*4 + 2*q + 1]);
}

// Decoder elementwise for layer L: gates+bias -> h,c; write fp16 hi/lo acts.
template<int L>
__device__ __forceinline__ void dec_ew(char* smem, int tid)
{
    constexpr int SA_SELF  = (L == 0) ? 200 : 264;
    constexpr int KIN      = (L == 0) ? 64 : 128;
    constexpr uint32_t AHI = (L == 0) ? OFF_A0H : (L == 1) ? OFF_A1H : OFF_A2H;
    constexpr uint32_t ALO = AHI + ((L == 0) ? 6400u : 8448u);
    constexpr uint32_t NHI = (L == 0) ? OFF_A1H : OFF_A2H;
    constexpr uint32_t NLO = NHI + 8448u;

    float* gates = (float*)(smem + OFF_GATES);
    const float* bias = (const float*)(smem + OFF_BIAS) + L*512;
    float* cb = (float*)(smem + OFF_C0 + L*8448u);
#pragma unroll
    for (int it = 0; it < 4; it++) {
        int idx = tid + it*512;
        if (idx < 14*128) {
            int r = idx >> 7, u = idx & 127;
            float gi = gates[r*520 + u      ] + bias[u      ];
            float gf = gates[r*520 + u + 128] + bias[u + 128];
            float gg = gates[r*520 + u + 256] + bias[u + 256];
            float go = gates[r*520 + u + 384] + bias[u + 384];
            float cv = sigf(gf)*cb[r*132 + u] + sigf(gi)*tanhff(gg);
            cb[r*132 + u] = cv;
            float hn = sigf(go)*tanhff(cv);
            __half hh = __float2half(hn);
            __half hl = __float2half(hn - __half2float(hh));
            ((__half*)(smem + AHI))[r*SA_SELF + KIN + u] = hh;
            ((__half*)(smem + ALO))[r*SA_SELF + KIN + u] = hl;
            if (L < 2) {
                ((__half*)(smem + NHI))[r*264 + u] = hh;
                ((__half*)(smem + NLO))[r*264 + u] = hl;
            } else {
                ((float*)(smem + OFF_H2))[r*132 + u] = hn;
            }
        }
    }
}

// ---------------------------------------------------------------------------
// Decoder persistent kernel (HMMA cells + scalar head).
// ---------------------------------------------------------------------------
__global__ void __launch_bounds__(512, 1) dec_kernel(
    const float* __restrict__ db0, const float* __restrict__ db1,
    const float* __restrict__ db2, const float* __restrict__ fb,
    float* __restrict__ out)
{
    extern __shared__ char smem[];
    const int tid = threadIdx.x;
    const int b0  = blockIdx.x * RPB;

    // zero A buffers (46592 B)
    for (int i = tid; i < 11648; i += 512)
        ((uint32_t*)(smem + OFF_A0H))[i] = 0u;
    for (int i = tid; i < FWT_FLOATS; i += 512)
        ((float*)(smem + OFF_FWT))[i] = g_fwt[i];
    {
        float* bias = (float*)(smem + OFF_BIAS);
        bias[tid]        = db0[tid];
        bias[512 + tid]  = db1[tid];
        bias[1024 + tid] = db2[tid];
    }
    __syncthreads();

    // load encoder-final state into A h-regions + c buffers
    for (int i = tid; i < 3*14*128; i += 512) {
        int u = i & 127;
        int r = (i >> 7) % 14;
        int l = i / (14*128);
        int b = b0 + r; if (b >= BATCH) b = BATCH - 1;
        float hv = g_state[l*BATCH*HID + b*HID + u];
        float cv = g_state[(3 + l)*BATCH*HID + b*HID + u];
        __half hh = __float2half(hv);
        __half hl = __float2half(hv - __half2float(hh));
        uint32_t ahi = (l == 0) ? OFF_A0H : (l == 1) ? OFF_A1H : OFF_A2H;
        uint32_t alo = ahi + ((l == 0) ? 6400u : 8448u);
        int sa  = (l == 0) ? 200 : 264;
        int kin = (l == 0) ? 64 : 128;
        ((__half*)(smem + ahi))[r*sa + kin + u] = hh;
        ((__half*)(smem + alo))[r*sa + kin + u] = hl;
        ((float*)(smem + OFF_C0 + (uint32_t)l*8448u))[r*132 + u] = cv;
    }
    __syncthreads();

    const float* fwts = (const float*)(smem + OFF_FWT);

    for (int t = 0; t < TSEQ; t++) {
        dec_gemm<12, 200>(smem, OFF_A0H, OFF_A0L, g_wd,            tid);
        __syncthreads();
        dec_ew<0>(smem, tid);
        __syncthreads();
        dec_gemm<16, 264>(smem, OFF_A1H, OFF_A1L, g_wd + 12*2048,  tid);
        __syncthreads();
        dec_ew<1>(smem, tid);
        __syncthreads();
        dec_gemm<16, 264>(smem, OFF_A2H, OFF_A2L, g_wd + 28*2048,  tid);
        __syncthreads();
        dec_ew<2>(smem, tid);
        __syncthreads();

        // head: pred = h2 @ fW^T + fb; write out (time-reversed) + feed back x
        {
            int d  = tid & 63;
            int rg = tid >> 6;
            const float* h2 = (const float*)(smem + OFF_H2);
            float fbv = (d < DVAR) ? fb[d] : 0.0f;
            float a0 = fbv, a1 = fbv;
            int r0 = rg, r1 = rg + 8;
#pragma unroll 4
            for (int u = 0; u < HID; u++) {
                float wv = fwts[(u << 6) + d];
                a0 += h2[r0*132 + u] * wv;
                a1 += h2[r1*132 + u] * wv;     // rows >=14 unused garbage, discarded
            }
            if (d < DVAR) {
                __half* xh = (__half*)(smem + OFF_A0H);
                __half* xl = (__half*)(smem + OFF_A0L);
                __half p0 = __float2half(a0);
                xh[r0*200 + d] = p0;
                xl[r0*200 + d] = __float2half(a0 - __half2float(p0));
                int bb = b0 + r0;
                if (bb < BATCH)
                    out[(bb*TSEQ + (TSEQ - 1 - t))*DVAR + d] = a0;
                if (r1 < RPB) {
                    __half p1 = __float2half(a1);
                    xh[r1*200 + d] = p1;
                    xl[r1*200 + d] = __float2half(a1 - __half2float(p1));
                    int bb1 = b0 + r1;
                    if (bb1 < BATCH)
                        out[(bb1*TSEQ + (TSEQ - 1 - t))*DVAR + d] = a1;
                }
            }
        }
        __syncthreads();
    }
}

// ---------------------------------------------------------------------------
extern "C" void kernel_launch(void* const* d_in, const int* in_sizes, int n_in,
                              void* d_out, int out_size)
{
    const float* src = (const float*)d_in[0];
    const float* eW0 = (const float*)d_in[1];
    const float* eU0 = (const float*)d_in[2];
    const float* eb0 = (const float*)d_in[3];
    const float* eW1 = (const float*)d_in[4];
    const float* eU1 = (const float*)d_in[5];
    const float* eb1 = (const float*)d_in[6];
    const float* eW2 = (const float*)d_in[7];
    const float* eU2 = (const float*)d_in[8];
    const float* eb2 = (const float*)d_in[9];
    const float* dW0 = (const float*)d_in[10];
    const float* dU0 = (const float*)d_in[11];
    const float* db0 = (const float*)d_in[12];
    const float* dW1 = (const float*)d_in[13];
    const float* dU1 = (const float*)d_in[14];
    const float* db1 = (const float*)d_in[15];
    const float* dW2 = (const float*)d_in[16];
    const float* dU2 = (const float*)d_in[17];
    const float* db2 = (const float*)d_in[18];
    const float* fW  = (const float*)d_in[19];
    const float* fb  = (const float*)d_in[20];
    float* out = (float*)d_out;

    const int GX64_SMEM  = 2*128*(64 + 8)*2;
    const int GX128_SMEM = 2*128*(128 + 8)*2;

    cudaFuncSetAttribute(gx_kernel<64,0>,  cudaFuncAttributeMaxDynamicSharedMemorySize, GX64_SMEM);
    cudaFuncSetAttribute(gx_kernel<128,1>, cudaFuncAttributeMaxDynamicSharedMemorySize, GX128_SMEM);
    cudaFuncSetAttribute(gx_kernel<128,2>, cudaFuncAttributeMaxDynamicSharedMemorySize, GX128_SMEM);
    cudaFuncSetAttribute(rec_kernel, cudaFuncAttributeMaxDynamicSharedMemorySize, R_SMEM_BYTES);
    cudaFuncSetAttribute(dec_kernel, cudaFuncAttributeMaxDynamicSharedMemorySize, DEC_SMEM);

    prep_kernel<<<1024, 256>>>(eW0, eU0, eW1, eU1, eW2, eU2,
                               dW0, dU0, dW1, dU1, dW2, dU2, fW);

    dim3 gxgrid(4, 1600);
    gx_kernel<64,0><<<gxgrid, 256, GX64_SMEM>>>(src);
    rec_kernel<<<NBLK, NTHR, R_SMEM_BYTES>>>(0, eb0, 1);
    gx_kernel<128,1><<<gxgrid, 256, GX128_SMEM>>>(src);
    rec_kernel<<<NBLK, NTHR, R_SMEM_BYTES>>>(1, eb1, 1);
    gx_kernel<128,2><<<gxgrid, 256, GX128_SMEM>>>(src);
    rec_kernel<<<NBLK, NTHR, R_SMEM_BYTES>>>(2, eb2, 0);
    dec_kernel<<<NBLK, 512, DEC_SMEM>>>(db0, db1, db2, fb, out);
}

// round 13
// speedup vs baseline: 1.8055x; 1.2429x over previous
#include <cuda_runtime.h>
#include <cuda_fp16.h>
#include <cstdint>

#define BATCH 2048
#define TSEQ  100
#define DVAR  51
#define HID   128
#define G4    512
#define RPB   14
#define NBLK  147

#define FWT_FLOATS (128*64)

// ---- decoder HMMA smem map (bytes) ----
#define OFF_FWT   0u
#define OFF_BIAS  32768u
#define OFF_A0H   38912u
#define OFF_A0L   45312u
#define OFF_A1H   51712u
#define OFF_A1L   60160u
#define OFF_A2H   68608u
#define OFF_A2L   77056u
#define OFF_GATES 85504u
#define OFF_C0    118784u
#define OFF_H2    144128u
#define DEC_SMEM  152576

// ---- encoder rec HMMA smem map (bytes) ----
#define RE_AHI    0u          /* 16*136 halves = 4352 */
#define RE_ALO    4352u
#define RE_GATES  8704u       /* 16*520 f32 = 33280 */
#define RE_C      41984u      /* 16*132 f32 = 8448 */
#define RE_BIAS   50432u      /* 512 f32 = 2048 */
#define RE_SMEM   52480

// ---------------- device scratch ----------------
__device__ float  g_fwt[FWT_FLOATS];
__device__ float  g_gx[(size_t)TSEQ*BATCH*G4];        // [m=t*2048+b][512]
__device__ float  g_hseq[(size_t)TSEQ*BATCH*HID];     // [m][128]
__device__ float  g_state[6*BATCH*HID];               // h0,h1,h2,c0,c1,c2
__device__ __half g_w16[3*512*128];                   // encoder Wih fp16 [l][j][k]
__device__ uint2  g_wd[45*2048];                      // decoder B-frag pack (+1 pad grp)
__device__ uint2  g_we[3*9*2048];                     // encoder Whh B-frag pack (+1 pad)

typedef unsigned long long ull;

__device__ __forceinline__ float sigf(float x) {
    return __fdividef(1.0f, 1.0f + __expf(-x));
}
__device__ __forceinline__ float tanhff(float x) {
    float e = __expf(2.0f * x);
    return 1.0f - __fdividef(2.0f, e + 1.0f);
}
__device__ __forceinline__ uint32_t smem_u32(const void* p) {
    uint32_t a;
    asm("{ .reg .u64 t; cvta.to.shared.u64 t, %1; cvt.u32.u64 %0, t; }" : "=r"(a) : "l"(p));
    return a;
}
__device__ __forceinline__ void ldsm4(uint32_t& r0, uint32_t& r1,
                                      uint32_t& r2, uint32_t& r3, uint32_t a) {
    asm volatile("ldmatrix.sync.aligned.m8n8.x4.shared.b16 {%0,%1,%2,%3}, [%4];"
                 : "=r"(r0), "=r"(r1), "=r"(r2), "=r"(r3) : "r"(a));
}
__device__ __forceinline__ void mma16816(float* d,
                                         uint32_t a0, uint32_t a1, uint32_t a2, uint32_t a3,
                                         uint32_t b0, uint32_t b1) {
    asm volatile(
        "mma.sync.aligned.m16n8k16.row.col.f32.f16.f16.f32 "
        "{%0,%1,%2,%3}, {%4,%5,%6,%7}, {%8,%9}, {%0,%1,%2,%3};"
        : "+f"(d[0]), "+f"(d[1]), "+f"(d[2]), "+f"(d[3])
        : "r"(a0), "r"(a1), "r"(a2), "r"(a3), "r"(b0), "r"(b1));
}

// ---------------------------------------------------------------------------
// Prep: fW^T, fp16 Wih images (gx), decoder + encoder B-fragment packs.
// ---------------------------------------------------------------------------
__global__ void prep_kernel(
    const float* w0, const float* u0, const float* w1, const float* u1,
    const float* w2, const float* u2, const float* w3, const float* u3,
    const float* w4, const float* u4, const float* w5, const float* u5,
    const float* fW)
{
    const float* WIH[3] = {w0, w1, w2};
    // fW^T padded
    for (int r2 = blockIdx.x*blockDim.x + threadIdx.x; r2 < FWT_FLOATS;
         r2 += gridDim.x*blockDim.x) {
        int u = r2 >> 6;
        int d = r2 & 63;
        g_fwt[r2] = (d < DVAR) ? fW[d*HID + u] : 0.0f;
    }
    // fp16 Wih images (encoder gx): [l][j 0..511][k 0..127]
    const int total2 = 3*512*128;
    for (int idx = blockIdx.x*blockDim.x + threadIdx.x; idx < total2;
         idx += gridDim.x*blockDim.x) {
        int l = idx >> 16;
        int r = idx & 65535;
        int j = r >> 7;
        int k = r & 127;
        int din = (l == 0) ? DVAR : HID;
        g_w16[idx] = __float2half((k < din) ? WIH[l][j*din + k] : 0.0f);
    }
    // decoder fp16 B-frag pack (x|h concatenated)
    const int total3 = 45*2048;
    for (int e = blockIdx.x*blockDim.x + threadIdx.x; e < total3;
         e += gridDim.x*blockDim.x) {
        int ksg = e >> 11;
        int r   = e & 2047;
        int n   = r >> 2;
        int q   = r & 3;
        unsigned short h4[4];
#pragma unroll
        for (int i = 0; i < 4; i++) {
            float v = 0.0f;
            if (ksg < 44) {
                int dl, ksl, kin, din;
                if (ksg < 12)      { dl = 0; ksl = ksg;      kin = 64;  din = DVAR; }
                else if (ksg < 28) { dl = 1; ksl = ksg - 12; kin = 128; din = HID; }
                else               { dl = 2; ksl = ksg - 28; kin = 128; din = HID; }
                int k = ksl*16 + q*2 + (i & 1) + ((i >> 1) << 3);
                const float* Wx = (dl == 0) ? w3 : (dl == 1) ? w4 : w5;
                const float* Wh = (dl == 0) ? u3 : (dl == 1) ? u4 : u5;
                if (k < kin) v = (k < din) ? Wx[n*din + k] : 0.0f;
                else         v = Wh[n*HID + (k - kin)];
            }
            h4[i] = __half_as_ushort(__float2half(v));
        }
        uint2 pk;
        pk.x = (uint32_t)h4[0] | ((uint32_t)h4[1] << 16);
        pk.y = (uint32_t)h4[2] | ((uint32_t)h4[3] << 16);
        g_wd[e] = pk;
    }
    // encoder Whh fp16 B-frag pack: [l][ksg 0..8][n][q], ksg 8 = zero pad
    const int total4 = 3*9*2048;
    for (int e = blockIdx.x*blockDim.x + threadIdx.x; e < total4;
         e += gridDim.x*blockDim.x) {
        int l   = e / (9*2048);
        int r0  = e - l*(9*2048);
        int ksg = r0 >> 11;
        int r   = r0 & 2047;
        int n   = r >> 2;
        int q   = r & 3;
        const float* Uh = (l == 0) ? u0 : (l == 1) ? u1 : u2;
        unsigned short h4[4];
#pragma unroll
        for (int i = 0; i < 4; i++) {
            float v = 0.0f;
            if (ksg < 8) {
                int k = ksg*16 + q*2 + (i & 1) + ((i >> 1) << 3);
                v = Uh[n*HID + k];
            }
            h4[i] = __half_as_ushort(__float2half(v));
        }
        uint2 pk;
        pk.x = (uint32_t)h4[0] | ((uint32_t)h4[1] << 16);
        pk.y = (uint32_t)h4[2] | ((uint32_t)h4[3] << 16);
        g_we[e] = pk;
    }
}

// ---------------------------------------------------------------------------
// Gx GEMM (HMMA) — unchanged (validated).
// ---------------------------------------------------------------------------
template<int KT, int MODE>
__global__ void __launch_bounds__(256, 1) gx_kernel(const float* __restrict__ src)
{
    extern __shared__ __half smh[];
    constexpr int SA = KT + 8;
    __half* As = smh;
    __half* Bs = smh + 128*SA;
    const int tid  = threadIdx.x;
    const int wid  = tid >> 5, lane = tid & 31;
    const int nb   = blockIdx.x * 128;
    const int m0   = blockIdx.y * 128;

    for (int idx = tid; idx < 128*KT; idx += 256) {
        int r = idx / KT, k = idx - r*KT;
        float v;
        if (MODE == 0) {
            int m = m0 + r, b = m & (BATCH-1), t = m >> 11;
            v = (k < DVAR) ? src[(b*TSEQ + t)*DVAR + k] : 0.0f;
        } else {
            v = g_hseq[(size_t)(m0 + r)*HID + k];
        }
        As[r*SA + k] = __float2half(v);
    }
    {
        const int L = (MODE == 0) ? 0 : MODE;
        const __half* ws = g_w16 + ((size_t)L*512 + nb)*128;
        for (int idx = tid; idx < 128*KT; idx += 256) {
            int r = idx / KT, k = idx - r*KT;
            Bs[r*SA + k] = ws[r*128 + k];
        }
    }
    __syncthreads();

    float acc[16][4];
#pragma unroll
    for (int i = 0; i < 16; i++)
#pragma unroll
        for (int q = 0; q < 4; q++) acc[i][q] = 0.0f;

    const uint32_t rsel = (lane & 15);
    const uint32_t csel = (uint32_t)(lane >> 4) * 8;
    const uint32_t aaddr = smem_u32(As) + (((uint32_t)wid*16 + rsel)*SA + csel)*2;
    const uint32_t baddr = smem_u32(Bs) + (rsel*SA + csel)*2;

#pragma unroll
    for (int ks = 0; ks < KT/16; ks++) {
        uint32_t a0, a1, a2, a3;
        ldsm4(a0, a1, a2, a3, aaddr + ks*32);
#pragma unroll
        for (int np = 0; np < 8; np++) {
            uint32_t b0, b1, b2, b3;
            ldsm4(b0, b1, b2, b3, baddr + (uint32_t)np*16*SA*2 + ks*32);
            mma16816(acc[2*np    ], a0, a1, a2, a3, b0, b2);
            mma16816(acc[2*np + 1], a0, a1, a2, a3, b1, b3);
        }
    }

    const int mrow = m0 + wid*16 + (lane >> 2);
    float* op  = g_gx + (size_t)mrow*G4 + nb + (lane & 3)*2;
    float* op2 = op + 8*(size_t)G4;
#pragma unroll
    for (int nt = 0; nt < 16; nt++) {
        *(float2*)(op  + nt*8) = make_float2(acc[nt][0], acc[nt][1]);
        *(float2*)(op2 + nt*8) = make_float2(acc[nt][2], acc[nt][3]);
    }
}

// ---------------------------------------------------------------------------
// HMMA GEMM (shared by decoder + encoder rec): gates[16][512] = A(hi+lo)@B.
// 16 warps, warp w owns 32 cols. B straight from L2 in fragment order.
// ---------------------------------------------------------------------------
template<int KS, int SA>
__device__ __forceinline__ void dec_gemm(char* smem, uint32_t ahi_off,
                                         uint32_t alo_off, uint32_t gates_off,
                                         const uint2* __restrict__ wd, int tid)
{
    const int lane  = tid & 31;
    const int wbase = (tid >> 5) * 4;

    float acc[16];
#pragma unroll
    for (int i = 0; i < 16; i++) acc[i] = 0.0f;

    const uint2* bp = wd + wbase*32 + lane;
    uint2 bc[4];
#pragma unroll
    for (int nt = 0; nt < 4; nt++) bc[nt] = bp[nt*32];

    const uint32_t abase = smem_u32(smem) + ((lane & 15)*SA + (lane >> 4)*8)*2;
    const uint32_t ahi = abase + ahi_off;
    const uint32_t alo = abase + alo_off;

#pragma unroll
    for (int ks = 0; ks < KS; ks++) {
        uint2 bn[4];
#pragma unroll
        for (int nt = 0; nt < 4; nt++) bn[nt] = bp[(ks + 1)*2048 + nt*32];
        uint32_t ah0, ah1, ah2, ah3, al0, al1, al2, al3;
        ldsm4(ah0, ah1, ah2, ah3, ahi + ks*32);
        ldsm4(al0, al1, al2, al3, alo + ks*32);
#pragma unroll
        for (int nt = 0; nt < 4; nt++) {
            mma16816(acc + nt*4, ah0, ah1, ah2, ah3, bc[nt].x, bc[nt].y);
            mma16816(acc + nt*4, al0, al1, al2, al3, bc[nt].x, bc[nt].y);
        }
#pragma unroll
        for (int nt = 0; nt < 4; nt++) bc[nt] = bn[nt];
    }

    float* gates = (float*)(smem + gates_off);
    const int row0 = lane >> 2;
    const int colb = wbase*8 + (lane & 3)*2;
#pragma unroll
    for (int nt = 0; nt < 4; nt++)
#pragma unroll
        for (int q = 0; q < 2; q++)
            *(float2*)(gates + (row0 + q*8)*520 + colb + nt*8)
                = make_float2(acc[nt*4 + 2*q], acc[nt*4 + 2*q + 1]);
}

// ---------------------------------------------------------------------------
// Encoder recurrent kernel (HMMA): gates = h@Whh; EW adds bias + Gx[t].
// ---------------------------------------------------------------------------
__global__ void __launch_bounds__(512, 1) rec_kernel(
    int layer, const float* __restrict__ bias, int writeseq)
{
    extern __shared__ char smem[];
    const int tid = threadIdx.x;
    const int b0  = blockIdx.x * RPB;

    // zero A hi/lo (8704 B) and c (8448 B)
    for (int i = tid; i < 2176; i += 512) ((uint32_t*)(smem + RE_AHI))[i] = 0u;
    for (int i = tid; i < 2112; i += 512) ((uint32_t*)(smem + RE_C  ))[i] = 0u;
    ((float*)(smem + RE_BIAS))[tid] = bias[tid];
    __syncthreads();

    const uint2* wd = g_we + layer*9*2048;
    float* gates = (float*)(smem + RE_GATES);
    float* cb    = (float*)(smem + RE_C);
    const float* bias_s = (const float*)(smem + RE_BIAS);

    for (int t = 0; t < TSEQ; t++) {
        dec_gemm<8, 136>(smem, RE_AHI, RE_ALO, RE_GATES, wd, tid);
        __syncthreads();

#pragma unroll
        for (int it = 0; it < 4; it++) {
            int idx = tid + it*512;
            if (idx < 14*128) {
                int r = idx >> 7, u = idx & 127;
                int b = b0 + r; if (b >= BATCH) b = BATCH - 1;
                const float* gx = g_gx + ((size_t)t*BATCH + b)*G4;
                float gi = gates[r*520 + u      ] + bias_s[u      ] + gx[u      ];
                float gf = gates[r*520 + u + 128] + bias_s[u + 128] + gx[u + 128];
                float gg = gates[r*520 + u + 256] + bias_s[u + 256] + gx[u + 256];
                float go = gates[r*520 + u + 384] + bias_s[u + 384] + gx[u + 384];
                float cv = sigf(gf)*cb[r*132 + u] + sigf(gi)*tanhff(gg);
                cb[r*132 + u] = cv;
                float hn = sigf(go)*tanhff(cv);
                __half hh = __float2half(hn);
                __half hl = __float2half(hn - __half2float(hh));
                ((__half*)(smem + RE_AHI))[r*136 + u] = hh;
                ((__half*)(smem + RE_ALO))[r*136 + u] = hl;
                if (writeseq)
                    g_hseq[((size_t)t*BATCH + b)*HID + u] = hn;
                if (t == TSEQ - 1) {
                    g_state[(layer    )*BATCH*HID + b*HID + u] = hn;
                    g_state[(3 + layer)*BATCH*HID + b*HID + u] = cv;
                }
            }
        }
        __syncthreads();
    }
}

// Decoder elementwise for layer L (unchanged, validated).
template<int L>
__device__ __forceinline__ void dec_ew(char* smem, int tid)
{
    constexpr int SA_SELF  = (L == 0) ? 200 : 264;
    constexpr int KIN      = (L == 0) ? 64 : 128;
    constexpr uint32_t AHI = (L == 0) ? OFF_A0H : (L == 1) ? OFF_A1H : OFF_A2H;
    constexpr uint32_t ALO = AHI + ((L == 0) ? 6400u : 8448u);
    constexpr uint32_t NHI = (L == 0) ? OFF_A1H : OFF_A2H;
    constexpr uint32_t NLO = NHI + 8448u;

    float* gates = (float*)(smem + OFF_GATES);
    const float* bias = (const float*)(smem + OFF_BIAS) + L*512;
    float* cb = (float*)(smem + OFF_C0 + L*8448u);
#pragma unroll
    for (int it = 0; it < 4; it++) {
        int idx = tid + it*512;
        if (idx < 14*128) {
            int r = idx >> 7, u = idx & 127;
            float gi = gates[r*520 + u      ] + bias[u      ];
            float gf = gates[r*520 + u + 128] + bias[u + 128];
            float gg = gates[r*520 + u + 256] + bias[u + 256];
            float go = gates[r*520 + u + 384] + bias[u + 384];
            float cv = sigf(gf)*cb[r*132 + u] + sigf(gi)*tanhff(gg);
            cb[r*132 + u] = cv;
            float hn = sigf(go)*tanhff(cv);
            __half hh = __float2half(hn);
            __half hl = __float2half(hn - __half2float(hh));
            ((__half*)(smem + AHI))[r*SA_SELF + KIN + u] = hh;
            ((__half*)(smem + ALO))[r*SA_SELF + KIN + u] = hl;
            if (L < 2) {
                ((__half*)(smem + NHI))[r*264 + u] = hh;
                ((__half*)(smem + NLO))[r*264 + u] = hl;
            } else {
                ((float*)(smem + OFF_H2))[r*132 + u] = hn;
            }
        }
    }
}

// ---------------------------------------------------------------------------
// Decoder persistent kernel (unchanged, validated).
// ---------------------------------------------------------------------------
__global__ void __launch_bounds__(512, 1) dec_kernel(
    const float* __restrict__ db0, const float* __restrict__ db1,
    const float* __restrict__ db2, const float* __restrict__ fb,
    float* __restrict__ out)
{
    extern __shared__ char smem[];
    const int tid = threadIdx.x;
    const int b0  = blockIdx.x * RPB;

    for (int i = tid; i < 11648; i += 512)
        ((uint32_t*)(smem + OFF_A0H))[i] = 0u;
    for (int i = tid; i < FWT_FLOATS; i += 512)
        ((float*)(smem + OFF_FWT))[i] = g_fwt[i];
    {
        float* bias = (float*)(smem + OFF_BIAS);
        bias[tid]        = db0[tid];
        bias[512 + tid]  = db1[tid];
        bias[1024 + tid] = db2[tid];
    }
    __syncthreads();

    for (int i = tid; i < 3*14*128; i += 512) {
        int u = i & 127;
        int r = (i >> 7) % 14;
        int l = i / (14*128);
        int b = b0 + r; if (b >= BATCH) b = BATCH - 1;
        float hv = g_state[l*BATCH*HID + b*HID + u];
        float cv = g_state[(3 + l)*BATCH*HID + b*HID + u];
        __half hh = __float2half(hv);
        __half hl = __float2half(hv - __half2float(hh));
        uint32_t ahi = (l == 0) ? OFF_A0H : (l == 1) ? OFF_A1H : OFF_A2H;
        uint32_t alo = ahi + ((l == 0) ? 6400u : 8448u);
        int sa  = (l == 0) ? 200 : 264;
        int kin = (l == 0) ? 64 : 128;
        ((__half*)(smem + ahi))[r*sa + kin + u] = hh;
        ((__half*)(smem + alo))[r*sa + kin + u] = hl;
        ((float*)(smem + OFF_C0 + (uint32_t)l*8448u))[r*132 + u] = cv;
    }
    __syncthreads();

    const float* fwts = (const float*)(smem + OFF_FWT);

    for (int t = 0; t < TSEQ; t++) {
        dec_gemm<12, 200>(smem, OFF_A0H, OFF_A0L, OFF_GATES, g_wd,           tid);
        __syncthreads();
        dec_ew<0>(smem, tid);
        __syncthreads();
        dec_gemm<16, 264>(smem, OFF_A1H, OFF_A1L, OFF_GATES, g_wd + 12*2048, tid);
        __syncthreads();
        dec_ew<1>(smem, tid);
        __syncthreads();
        dec_gemm<16, 264>(smem, OFF_A2H, OFF_A2L, OFF_GATES, g_wd + 28*2048, tid);
        __syncthreads();
        dec_ew<2>(smem, tid);
        __syncthreads();

        {
            int d  = tid & 63;
            int rg = tid >> 6;
            const float* h2 = (const float*)(smem + OFF_H2);
            float fbv = (d < DVAR) ? fb[d] : 0.0f;
            float a0 = fbv, a1 = fbv;
            int r0 = rg, r1 = rg + 8;
#pragma unroll 4
            for (int u = 0; u < HID; u++) {
                float wv = fwts[(u << 6) + d];
                a0 += h2[r0*132 + u] * wv;
                a1 += h2[r1*132 + u] * wv;
            }
            if (d < DVAR) {
                __half* xh = (__half*)(smem + OFF_A0H);
                __half* xl = (__half*)(smem + OFF_A0L);
                __half p0 = __float2half(a0);
                xh[r0*200 + d] = p0;
                xl[r0*200 + d] = __float2half(a0 - __half2float(p0));
                int bb = b0 + r0;
                if (bb < BATCH)
                    out[(bb*TSEQ + (TSEQ - 1 - t))*DVAR + d] = a0;
                if (r1 < RPB) {
                    __half p1 = __float2half(a1);
                    xh[r1*200 + d] = p1;
                    xl[r1*200 + d] = __float2half(a1 - __half2float(p1));
                    int bb1 = b0 + r1;
                    if (bb1 < BATCH)
                        out[(bb1*TSEQ + (TSEQ - 1 - t))*DVAR + d] = a1;
                }
            }
        }
        __syncthreads();
    }
}

// ---------------------------------------------------------------------------
extern "C" void kernel_launch(void* const* d_in, const int* in_sizes, int n_in,
                              void* d_out, int out_size)
{
    const float* src = (const float*)d_in[0];
    const float* eW0 = (const float*)d_in[1];
    const float* eU0 = (const float*)d_in[2];
    const float* eb0 = (const float*)d_in[3];
    const float* eW1 = (const float*)d_in[4];
    const float* eU1 = (const float*)d_in[5];
    const float* eb1 = (const float*)d_in[6];
    const float* eW2 = (const float*)d_in[7];
    const float* eU2 = (const float*)d_in[8];
    const float* eb2 = (const float*)d_in[9];
    const float* dW0 = (const float*)d_in[10];
    const float* dU0 = (const float*)d_in[11];
    const float* db0 = (const float*)d_in[12];
    const float* dW1 = (const float*)d_in[13];
    const float* dU1 = (const float*)d_in[14];
    const float* db1 = (const float*)d_in[15];
    const float* dW2 = (const float*)d_in[16];
    const float* dU2 = (const float*)d_in[17];
    const float* db2 = (const float*)d_in[18];
    const float* fW  = (const float*)d_in[19];
    const float* fb  = (const float*)d_in[20];
    float* out = (float*)d_out;

    const int GX64_SMEM  = 2*128*(64 + 8)*2;
    const int GX128_SMEM = 2*128*(128 + 8)*2;

    cudaFuncSetAttribute(gx_kernel<64,0>,  cudaFuncAttributeMaxDynamicSharedMemorySize, GX64_SMEM);
    cudaFuncSetAttribute(gx_kernel<128,1>, cudaFuncAttributeMaxDynamicSharedMemorySize, GX128_SMEM);
    cudaFuncSetAttribute(gx_kernel<128,2>, cudaFuncAttributeMaxDynamicSharedMemorySize, GX128_SMEM);
    cudaFuncSetAttribute(rec_kernel, cudaFuncAttributeMaxDynamicSharedMemorySize, RE_SMEM);
    cudaFuncSetAttribute(dec_kernel, cudaFuncAttributeMaxDynamicSharedMemorySize, DEC_SMEM);

    prep_kernel<<<1024, 256>>>(eW0, eU0, eW1, eU1, eW2, eU2,
                               dW0, dU0, dW1, dU1, dW2, dU2, fW);

    dim3 gxgrid(4, 1600);
    gx_kernel<64,0><<<gxgrid, 256, GX64_SMEM>>>(src);
    rec_kernel<<<NBLK, 512, RE_SMEM>>>(0, eb0, 1);
    gx_kernel<128,1><<<gxgrid, 256, GX128_SMEM>>>(src);
    rec_kernel<<<NBLK, 512, RE_SMEM>>>(1, eb1, 1);
    gx_kernel<128,2><<<gxgrid, 256, GX128_SMEM>>>(src);
    rec_kernel<<<NBLK, 512, RE_SMEM>>>(2, eb2, 0);
    dec_kernel<<<NBLK, 512, DEC_SMEM>>>(db0, db1, db2, fb, out);
}